// round 3
// baseline (speedup 1.0000x reference)
#include <cuda_runtime.h>
#include <math.h>

// Problem constants
#define DIRS 2
#define BB   32
#define TT   512
#define DD   512
#define HH   512
#define G4   2048            // 4*H
#define TBM  16384           // T*B
#define NBLK 128             // persistent scan grid size (<= 148 SMs, all resident)

static const size_t OUT_HN = (size_t)BB * TT * 2 * HH;   // 16777216
static const size_t OUT_CN = OUT_HN + 4ULL * BB * HH;    // 16842752

typedef unsigned long long ull;

// ---------------- scratch (static device globals; no allocation) ----------------
__device__ __align__(16) float g_xm[(size_t)TBM * 1024];           // masked layer input [T*B][K<=1024]
__device__ __align__(16) float g_xg[(size_t)DIRS * TBM * G4];      // input-projection gates per dir
__device__ __align__(16) float g_y[(size_t)DIRS * TBM * HH];       // layer-0 outputs per dir [t][b][h]
__device__ __align__(16) float g_whhT[(size_t)2 * DIRS * HH * HH * 4]; // [layer][dir][hc][k][gate] = 4194304 floats
__device__ __align__(16) float g_part[8 * DIRS * BB * G4];         // K-split partials
__device__ __align__(16) float g_hmT[DIRS * HH * BB];              // [dir][k][b] = h*mask_h transposed

// grid barrier state
__device__ unsigned g_bar_count = 0;
__device__ unsigned g_bar_gen = 0;

// ---------------- f32x2 helpers ----------------
__device__ __forceinline__ ull pack2(float x, float y) {
    ull r;
    asm("mov.b64 %0, {%1, %2};" : "=l"(r) : "r"(__float_as_uint(x)), "r"(__float_as_uint(y)));
    return r;
}
__device__ __forceinline__ ull splat2(float x) {
    ull r; unsigned u = __float_as_uint(x);
    asm("mov.b64 %0, {%1, %1};" : "=l"(r) : "r"(u));
    return r;
}
__device__ __forceinline__ ull ffma2(ull a, ull b, ull c) {
    ull d;
    asm("fma.rn.f32x2 %0, %1, %2, %3;" : "=l"(d) : "l"(a), "l"(b), "l"(c));
    return d;
}
__device__ __forceinline__ float lo2(ull v) { return __uint_as_float((unsigned)(v & 0xffffffffu)); }
__device__ __forceinline__ float hi2(ull v) { return __uint_as_float((unsigned)(v >> 32)); }
__device__ __forceinline__ float sigmoidf_(float x) { return 1.0f / (1.0f + expf(-x)); }

// sense-reversing grid barrier; all threads call. Callers must __threadfence()
// before this if they need their global stores visible past the barrier.
__device__ __forceinline__ void grid_barrier() {
    __syncthreads();
    if (threadIdx.x == 0) {
        volatile unsigned* genp = &g_bar_gen;
        unsigned old = *genp;
        unsigned t = atomicAdd(&g_bar_count, 1u);
        if (t == NBLK - 1) {
            g_bar_count = 0;
            __threadfence();
            atomicAdd(&g_bar_gen, 1u);
        } else {
            while (*genp == old) { __nanosleep(20); }
        }
        __threadfence();
    }
    __syncthreads();
}

// ---------------- prep kernels ----------------

// g_xm[(t*B+b)*512 + k] = x[b][t][k] * mask_x[b][k]
__global__ void k_mask_in0(const float* __restrict__ x, const float* __restrict__ mask_x) {
    int gid = blockIdx.x * 256 + threadIdx.x;          // < 8388608
    int k = gid & 511; int b = (gid >> 9) & 31; int t = gid >> 14;
    g_xm[gid] = x[((size_t)b * TT + t) * DD + k] * mask_x[b * 512 + k];
}

// g_whhT[layer][dir][hc][k][g] = w_hh[dir][g*H+hc][k]   (4194304 elements)
__global__ void k_build_whhT(const float* __restrict__ w0, const float* __restrict__ w1) {
    int gid = blockIdx.x * 256 + threadIdx.x;          // < 4194304
    int g = gid & 3; int k = (gid >> 2) & 511; int hc = (gid >> 11) & 511;
    int dir = (gid >> 20) & 1; int layer = (gid >> 21) & 1;
    const float* w = layer ? w1 : w0;
    g_whhT[gid] = w[(size_t)dir * G4 * HH + (size_t)(g * HH + hc) * HH + k];
}

// g_xm[(t*B+b)*1024 + j] = concat(y_fwd,y_bwd)[t][b][j] * mask_out[b][j]
__global__ void k_build_in1(const float* __restrict__ mask_out) {
    int gid = blockIdx.x * 256 + threadIdx.x;          // < 16777216
    int j = gid & 1023; int b = (gid >> 10) & 31; int t = gid >> 15;
    int dir = j >> 9; int hc = j & 511;
    g_xm[gid] = g_y[(size_t)dir * TBM * HH + (size_t)(t * BB + b) * HH + hc] * mask_out[b * 1024 + j];
}

// ---------------- input-projection GEMM: C[M,2048] = A[M,K] * W[2048,K]^T + bias ----------------
__global__ void __launch_bounds__(256, 2) gemm_nt_bias(
    const float* __restrict__ A, const float* __restrict__ W,
    const float* __restrict__ bias, float* __restrict__ C, int K)
{
    __shared__ __align__(16) float As[8][128];
    __shared__ __align__(16) float Ws[8][128];
    const int tid = threadIdx.x;
    const int m0 = blockIdx.y * 128;
    const int n0 = blockIdx.x * 128;
    const int lrow = tid >> 1;
    const int lseg = (tid & 1) * 4;
    const float* Ap = A + (size_t)(m0 + lrow) * K + lseg;
    const float* Wp = W + (size_t)(n0 + lrow) * K + lseg;
    const int ty = tid >> 4, tx = tid & 15;

    ull acc[8][4];
#pragma unroll
    for (int i = 0; i < 8; i++) { acc[i][0] = 0; acc[i][1] = 0; acc[i][2] = 0; acc[i][3] = 0; }

    for (int k0 = 0; k0 < K; k0 += 8) {
        float4 av = *(const float4*)(Ap + k0);
        float4 wv = *(const float4*)(Wp + k0);
        __syncthreads();
        As[lseg + 0][lrow] = av.x; As[lseg + 1][lrow] = av.y;
        As[lseg + 2][lrow] = av.z; As[lseg + 3][lrow] = av.w;
        Ws[lseg + 0][lrow] = wv.x; Ws[lseg + 1][lrow] = wv.y;
        Ws[lseg + 2][lrow] = wv.z; Ws[lseg + 3][lrow] = wv.w;
        __syncthreads();
#pragma unroll
        for (int kk = 0; kk < 8; kk++) {
            float4 a0 = *(const float4*)&As[kk][ty * 8];
            float4 a1 = *(const float4*)&As[kk][ty * 8 + 4];
            float4 b0 = *(const float4*)&Ws[kk][tx * 8];
            float4 b1 = *(const float4*)&Ws[kk][tx * 8 + 4];
            ull bp0 = pack2(b0.x, b0.y), bp1 = pack2(b0.z, b0.w);
            ull bp2 = pack2(b1.x, b1.y), bp3 = pack2(b1.z, b1.w);
            float aa[8] = {a0.x, a0.y, a0.z, a0.w, a1.x, a1.y, a1.z, a1.w};
#pragma unroll
            for (int i = 0; i < 8; i++) {
                ull a2 = splat2(aa[i]);
                acc[i][0] = ffma2(a2, bp0, acc[i][0]);
                acc[i][1] = ffma2(a2, bp1, acc[i][1]);
                acc[i][2] = ffma2(a2, bp2, acc[i][2]);
                acc[i][3] = ffma2(a2, bp3, acc[i][3]);
            }
        }
    }
    float bs[8];
#pragma unroll
    for (int j = 0; j < 8; j++) bs[j] = bias[n0 + tx * 8 + j];
#pragma unroll
    for (int i = 0; i < 8; i++) {
        float* Crow = C + (size_t)(m0 + ty * 8 + i) * G4 + n0 + tx * 8;
        float4 v0 = make_float4(lo2(acc[i][0]) + bs[0], hi2(acc[i][0]) + bs[1],
                                lo2(acc[i][1]) + bs[2], hi2(acc[i][1]) + bs[3]);
        float4 v1 = make_float4(lo2(acc[i][2]) + bs[4], hi2(acc[i][2]) + bs[5],
                                lo2(acc[i][3]) + bs[6], hi2(acc[i][3]) + bs[7]);
        *(float4*)(Crow) = v0;
        *(float4*)(Crow + 4) = v1;
    }
}

// ---------------- persistent scan: one launch runs all 512 timesteps of a layer ----------------
// Grid: 128 blocks x 256 threads, all co-resident -> software grid barrier.
// Phase1 per block: (kc,jt,dir) slice of recurrent GEMM (32b x 64hc x 4g over 64k).
// Phase2 per thread: one (dir,b,hc); c/h state held in registers across steps.
__global__ void __launch_bounds__(256, 1) lstm_scan(int layer, float* __restrict__ out,
                                                    const float* __restrict__ mask_h) {
    const int bx = blockIdx.x;
    const int tid = threadIdx.x;

    // ---- phase1 identity ----
    const int kc = bx & 7;
    const int jt = (bx >> 3) & 7;
    const int dirb = bx >> 6;
    const int bg = tid & 7;                 // 8 groups of 4 b
    const int jg = tid >> 3;                // 32 groups of 2 hc
    const int hc0 = jt * 64 + jg * 2;
    const float4* w0 = (const float4*)g_whhT + (size_t)layer * 524288
                       + ((size_t)dirb * 512 + hc0) * 512 + kc * 64;
    const float4* w1 = w0 + 512;
    float4* pdst = (float4*)g_part + (size_t)(kc * 2 + dirb) * 32 * 512;
    const float4* src = (const float4*)g_hmT + dirb * 4096 + kc * 512;
    __shared__ __align__(16) float4 s_hm[512];

    // ---- phase2 identity ----
    const int gid = bx * 256 + tid;         // < 32768
    const int dir2 = gid >> 14;
    const int rem = gid & 16383;
    const int b2 = rem >> 9;
    const int hc2 = rem & 511;
    const float mh = mask_h[(size_t)layer * 16384 + rem];
    float h_reg = 0.f, c_reg = 0.f;

    // init hmT(t=-1) = 0
    g_hmT[dir2 * 16384 + hc2 * 32 + b2] = 0.f;
    __threadfence();
    grid_barrier();

    for (int s = 0; s < TT; s++) {
        // ------- phase 1 -------
        s_hm[tid] = src[tid];
        s_hm[tid + 256] = src[tid + 256];
        __syncthreads();

        ull acc[4][4];
#pragma unroll
        for (int i = 0; i < 4; i++) { acc[i][0] = 0; acc[i][1] = 0; acc[i][2] = 0; acc[i][3] = 0; }

#pragma unroll 4
        for (int kk = 0; kk < 64; kk++) {
            float4 ha = s_hm[kk * 8 + bg];
            float4 wa = __ldg(w0 + kk);
            float4 wb = __ldg(w1 + kk);
            ull wa0 = pack2(wa.x, wa.y), wa1 = pack2(wa.z, wa.w);
            ull wb0 = pack2(wb.x, wb.y), wb1 = pack2(wb.z, wb.w);
            float hv[4] = {ha.x, ha.y, ha.z, ha.w};
#pragma unroll
            for (int ib = 0; ib < 4; ib++) {
                ull h2 = splat2(hv[ib]);
                acc[ib][0] = ffma2(h2, wa0, acc[ib][0]);
                acc[ib][1] = ffma2(h2, wa1, acc[ib][1]);
                acc[ib][2] = ffma2(h2, wb0, acc[ib][2]);
                acc[ib][3] = ffma2(h2, wb1, acc[ib][3]);
            }
        }
        const int bbase = bg * 4;
#pragma unroll
        for (int ib = 0; ib < 4; ib++) {
            int b = bbase + ib;
            pdst[(size_t)b * 512 + hc0] =
                make_float4(lo2(acc[ib][0]), hi2(acc[ib][0]), lo2(acc[ib][1]), hi2(acc[ib][1]));
            pdst[(size_t)b * 512 + hc0 + 1] =
                make_float4(lo2(acc[ib][2]), hi2(acc[ib][2]), lo2(acc[ib][3]), hi2(acc[ib][3]));
        }
        __threadfence();
        grid_barrier();

        // ------- phase 2 -------
        const int t = dir2 ? (TT - 1 - s) : s;
        const float4* p4 = (const float4*)g_part;
        float4 sum = make_float4(0.f, 0.f, 0.f, 0.f);
#pragma unroll
        for (int k8 = 0; k8 < 8; k8++) {
            float4 v = p4[((size_t)(k8 * 2 + dir2) * 32 + b2) * 512 + hc2];
            sum.x += v.x; sum.y += v.y; sum.z += v.z; sum.w += v.w;
        }
        const float* xgb = g_xg + ((size_t)dir2 * TBM + (size_t)t * BB + b2) * G4 + hc2;
        float gi = sum.x + xgb[0];
        float gf = sum.y + xgb[HH];
        float gg = sum.z + xgb[2 * HH];
        float go = sum.w + xgb[3 * HH];

        c_reg = sigmoidf_(gf) * c_reg + sigmoidf_(gi) * tanhf(gg);
        h_reg = sigmoidf_(go) * tanhf(c_reg);

        g_hmT[dir2 * 16384 + hc2 * 32 + b2] = h_reg * mh;
        if (layer == 0)
            g_y[(size_t)dir2 * TBM * HH + ((size_t)t * BB + b2) * HH + hc2] = h_reg;
        else
            out[((size_t)b2 * TT + t) * (2 * HH) + dir2 * HH + hc2] = h_reg;

        __threadfence();
        grid_barrier();
    }

    // final hn / cn
    out[OUT_HN + (size_t)layer * 32768 + gid] = h_reg;
    out[OUT_CN + (size_t)layer * 32768 + gid] = c_reg;
}

// ---------------- launcher ----------------
extern "C" void kernel_launch(void* const* d_in, const int* in_sizes, int n_in,
                              void* d_out, int out_size) {
    (void)in_sizes; (void)n_in; (void)out_size;
    const float* x       = (const float*)d_in[0];
    const float* mask_x  = (const float*)d_in[1];
    const float* mask_out= (const float*)d_in[2];
    const float* mask_h  = (const float*)d_in[3];
    const float* w_ih_l0 = (const float*)d_in[4];
    const float* w_hh_l0 = (const float*)d_in[5];
    const float* b_l0    = (const float*)d_in[6];
    const float* w_ih_l1 = (const float*)d_in[7];
    const float* w_hh_l1 = (const float*)d_in[8];
    const float* b_l1    = (const float*)d_in[9];
    float* out = (float*)d_out;

    float *p_xm = nullptr, *p_xg = nullptr;
    cudaGetSymbolAddress((void**)&p_xm, g_xm);
    cudaGetSymbolAddress((void**)&p_xg, g_xg);

    // weight transpose + layer-0 masked input
    k_build_whhT<<<4194304 / 256, 256>>>(w_hh_l0, w_hh_l1);
    k_mask_in0<<<8388608 / 256, 256>>>(x, mask_x);

    // layer-0 input projections
    for (int dir = 0; dir < 2; dir++)
        gemm_nt_bias<<<dim3(16, 128), 256>>>(p_xm, w_ih_l0 + (size_t)dir * G4 * DD,
                                             b_l0 + dir * G4,
                                             p_xg + (size_t)dir * TBM * G4, DD);

    // layer-0 scan (persistent)
    lstm_scan<<<NBLK, 256>>>(0, out, mask_h);

    // layer-1 input = concat(y_fwd, y_bwd) * mask_out, then projections
    k_build_in1<<<16777216 / 256, 256>>>(mask_out);
    for (int dir = 0; dir < 2; dir++)
        gemm_nt_bias<<<dim3(16, 128), 256>>>(p_xm, w_ih_l1 + (size_t)dir * G4 * (2 * HH),
                                             b_l1 + dir * G4,
                                             p_xg + (size_t)dir * TBM * G4, 2 * HH);

    // layer-1 scan (persistent, writes final output directly)
    lstm_scan<<<NBLK, 256>>>(1, out, mask_h);
}

// round 4
// speedup vs baseline: 1.1875x; 1.1875x over previous
#include <cuda_runtime.h>
#include <math.h>

// Problem constants
#define DIRS 2
#define BB   32
#define TT   512
#define DD   512
#define HH   512
#define G4   2048            // 4*H
#define TBM  16384           // T*B
#define NBLK 128             // persistent scan grid (1 block/SM, all co-resident)

static const size_t OUT_HN = (size_t)BB * TT * 2 * HH;   // 16777216
static const size_t OUT_CN = OUT_HN + 4ULL * BB * HH;    // 16842752

typedef unsigned long long ull;

// ---------------- scratch (static device globals; no allocation) ----------------
__device__ __align__(16) float g_xm[(size_t)TBM * 1024];
__device__ __align__(16) float g_xg[(size_t)DIRS * TBM * G4];
__device__ __align__(16) float g_y[(size_t)DIRS * TBM * HH];
__device__ __align__(16) float g_whhT[(size_t)2 * DIRS * HH * HH * 4]; // [layer][dir][hc][k][gate]
__device__ __align__(16) float g_part[4 * DIRS * BB * G4];             // kc=4 K-split partials (2MB)
__device__ __align__(16) float g_hmT[DIRS * HH * BB];                  // [dir][k][b]

// grid barrier state
__device__ unsigned g_bar_count = 0;
__device__ unsigned g_bar_gen = 0;

// ---------------- f32x2 helpers ----------------
__device__ __forceinline__ ull pack2(float x, float y) {
    ull r;
    asm("mov.b64 %0, {%1, %2};" : "=l"(r) : "r"(__float_as_uint(x)), "r"(__float_as_uint(y)));
    return r;
}
__device__ __forceinline__ ull splat2(float x) {
    ull r; unsigned u = __float_as_uint(x);
    asm("mov.b64 %0, {%1, %1};" : "=l"(r) : "r"(u));
    return r;
}
__device__ __forceinline__ ull ffma2(ull a, ull b, ull c) {
    ull d;
    asm("fma.rn.f32x2 %0, %1, %2, %3;" : "=l"(d) : "l"(a), "l"(b), "l"(c));
    return d;
}
__device__ __forceinline__ float lo2(ull v) { return __uint_as_float((unsigned)(v & 0xffffffffu)); }
__device__ __forceinline__ float hi2(ull v) { return __uint_as_float((unsigned)(v >> 32)); }
__device__ __forceinline__ float sigmoidf_(float x) { return 1.0f / (1.0f + expf(-x)); }

// sense-reversing grid barrier; tight spin, fences carry release/acquire + L1 IVALL.
__device__ __forceinline__ void grid_barrier() {
    __syncthreads();
    if (threadIdx.x == 0) {
        __threadfence();                          // release block's stores (gpu scope)
        volatile unsigned* genp = &g_bar_gen;
        unsigned old = *genp;
        unsigned t = atomicAdd(&g_bar_count, 1u);
        if (t == NBLK - 1) {
            g_bar_count = 0;
            __threadfence();
            g_bar_gen = old + 1;
        } else {
            while (*genp == old) {}
        }
        __threadfence();                          // acquire side (invalidates this SM's L1)
    }
    __syncthreads();
}

// ---------------- prep kernels ----------------
__global__ void k_mask_in0(const float* __restrict__ x, const float* __restrict__ mask_x) {
    int gid = blockIdx.x * 256 + threadIdx.x;          // < 8388608
    int k = gid & 511; int b = (gid >> 9) & 31; int t = gid >> 14;
    g_xm[gid] = x[((size_t)b * TT + t) * DD + k] * mask_x[b * 512 + k];
}

__global__ void k_build_whhT(const float* __restrict__ w0, const float* __restrict__ w1) {
    int gid = blockIdx.x * 256 + threadIdx.x;          // < 4194304
    int g = gid & 3; int k = (gid >> 2) & 511; int hc = (gid >> 11) & 511;
    int dir = (gid >> 20) & 1; int layer = (gid >> 21) & 1;
    const float* w = layer ? w1 : w0;
    g_whhT[gid] = w[(size_t)dir * G4 * HH + (size_t)(g * HH + hc) * HH + k];
}

__global__ void k_build_in1(const float* __restrict__ mask_out) {
    int gid = blockIdx.x * 256 + threadIdx.x;          // < 16777216
    int j = gid & 1023; int b = (gid >> 10) & 31; int t = gid >> 15;
    int dir = j >> 9; int hc = j & 511;
    g_xm[gid] = g_y[(size_t)dir * TBM * HH + (size_t)(t * BB + b) * HH + hc] * mask_out[b * 1024 + j];
}

// ---------------- input-projection GEMM: C[M,2048] = A[M,K] * W[2048,K]^T + bias ----------------
__global__ void __launch_bounds__(256, 2) gemm_nt_bias(
    const float* __restrict__ A, const float* __restrict__ W,
    const float* __restrict__ bias, float* __restrict__ C, int K)
{
    __shared__ __align__(16) float As[8][128];
    __shared__ __align__(16) float Ws[8][128];
    const int tid = threadIdx.x;
    const int m0 = blockIdx.y * 128;
    const int n0 = blockIdx.x * 128;
    const int lrow = tid >> 1;
    const int lseg = (tid & 1) * 4;
    const float* Ap = A + (size_t)(m0 + lrow) * K + lseg;
    const float* Wp = W + (size_t)(n0 + lrow) * K + lseg;
    const int ty = tid >> 4, tx = tid & 15;

    ull acc[8][4];
#pragma unroll
    for (int i = 0; i < 8; i++) { acc[i][0] = 0; acc[i][1] = 0; acc[i][2] = 0; acc[i][3] = 0; }

    for (int k0 = 0; k0 < K; k0 += 8) {
        float4 av = *(const float4*)(Ap + k0);
        float4 wv = *(const float4*)(Wp + k0);
        __syncthreads();
        As[lseg + 0][lrow] = av.x; As[lseg + 1][lrow] = av.y;
        As[lseg + 2][lrow] = av.z; As[lseg + 3][lrow] = av.w;
        Ws[lseg + 0][lrow] = wv.x; Ws[lseg + 1][lrow] = wv.y;
        Ws[lseg + 2][lrow] = wv.z; Ws[lseg + 3][lrow] = wv.w;
        __syncthreads();
#pragma unroll
        for (int kk = 0; kk < 8; kk++) {
            float4 a0 = *(const float4*)&As[kk][ty * 8];
            float4 a1 = *(const float4*)&As[kk][ty * 8 + 4];
            float4 b0 = *(const float4*)&Ws[kk][tx * 8];
            float4 b1 = *(const float4*)&Ws[kk][tx * 8 + 4];
            ull bp0 = pack2(b0.x, b0.y), bp1 = pack2(b0.z, b0.w);
            ull bp2 = pack2(b1.x, b1.y), bp3 = pack2(b1.z, b1.w);
            float aa[8] = {a0.x, a0.y, a0.z, a0.w, a1.x, a1.y, a1.z, a1.w};
#pragma unroll
            for (int i = 0; i < 8; i++) {
                ull a2 = splat2(aa[i]);
                acc[i][0] = ffma2(a2, bp0, acc[i][0]);
                acc[i][1] = ffma2(a2, bp1, acc[i][1]);
                acc[i][2] = ffma2(a2, bp2, acc[i][2]);
                acc[i][3] = ffma2(a2, bp3, acc[i][3]);
            }
        }
    }
    float bs[8];
#pragma unroll
    for (int j = 0; j < 8; j++) bs[j] = bias[n0 + tx * 8 + j];
#pragma unroll
    for (int i = 0; i < 8; i++) {
        float* Crow = C + (size_t)(m0 + ty * 8 + i) * G4 + n0 + tx * 8;
        float4 v0 = make_float4(lo2(acc[i][0]) + bs[0], hi2(acc[i][0]) + bs[1],
                                lo2(acc[i][1]) + bs[2], hi2(acc[i][1]) + bs[3]);
        float4 v1 = make_float4(lo2(acc[i][2]) + bs[4], hi2(acc[i][2]) + bs[5],
                                lo2(acc[i][3]) + bs[6], hi2(acc[i][3]) + bs[7]);
        *(float4*)(Crow) = v0;
        *(float4*)(Crow + 4) = v1;
    }
}

// ---------------- persistent scan ----------------
// Grid: 128 blocks x 256 threads. Block = (kc 4, jt 16, dir 2): 32 hc x 4 gates x 32 b over K=128.
// Weights (64KB) live in SMEM for all 512 steps (immune to the per-step L1 invalidate).
// Thread tile: 1 hc x 4 gates x 4 b. State c/h in registers in phase-2 identity.
#define SW_STRIDE 132   // float4 stride per jg row (padded vs 128 to break bank conflicts)

__global__ void __launch_bounds__(256, 1) lstm_scan(int layer, float* __restrict__ out,
                                                    const float* __restrict__ mask_h) {
    extern __shared__ __align__(16) float4 smem4[];
    float4* sw4 = smem4;                       // 32 * 132 float4 = 67584 B
    float4* s_hm = smem4 + 32 * SW_STRIDE;     // 1024 float4 = 16384 B

    const int bx = blockIdx.x;
    const int tid = threadIdx.x;

    // ---- phase1 identity ----
    const int kc = bx & 3;                 // K chunk (128 k each)
    const int jt = (bx >> 2) & 15;         // hc tile of 32
    const int dirb = bx >> 6;
    const int bg = tid & 7;                // 8 groups of 4 b
    const int jg = tid >> 3;               // 32 hc within tile
    const int hc1 = jt * 32 + jg;
    const float4* whhT4 = (const float4*)g_whhT;
    float4* pdst = (float4*)g_part + (size_t)(kc * 2 + dirb) * 32 * 512;
    const float4* hsrc = (const float4*)g_hmT + dirb * 4096 + kc * 1024;

    // load weights into smem once: [jg][kk] float4 = 4 gates of (dir,hc1) at k=kc*128+kk
    {
        const size_t rowbase = ((size_t)layer * 1024 + (size_t)dirb * 512) * 512;
        for (int idx = tid; idx < 4096; idx += 256) {
            int j = idx >> 7, kk = idx & 127;
            sw4[j * SW_STRIDE + kk] = whhT4[rowbase + (size_t)(jt * 32 + j) * 512 + kc * 128 + kk];
        }
    }

    // ---- phase2 identity ----
    const int gid = bx * 256 + tid;        // < 32768
    const int dir2 = gid >> 14;
    const int rem = gid & 16383;
    const int b2 = rem >> 9;
    const int hc2 = rem & 511;
    const float mh = mask_h[(size_t)layer * 16384 + rem];
    float h_reg = 0.f, c_reg = 0.f;

    // init hmT(t=-1) = 0
    g_hmT[dir2 * 16384 + hc2 * 32 + b2] = 0.f;
    grid_barrier();

    for (int s = 0; s < TT; s++) {
        // ------- phase 1: partial recurrent GEMM -------
#pragma unroll
        for (int i = 0; i < 4; i++) s_hm[tid + i * 256] = __ldcg(hsrc + tid + i * 256);
        __syncthreads();

        ull acc[4][2];
#pragma unroll
        for (int i = 0; i < 4; i++) { acc[i][0] = 0; acc[i][1] = 0; }

#pragma unroll 8
        for (int kk = 0; kk < 128; kk++) {
            float4 ha = s_hm[kk * 8 + bg];
            float4 w = sw4[jg * SW_STRIDE + kk];
            ull w01 = pack2(w.x, w.y);   // gates i,f
            ull w23 = pack2(w.z, w.w);   // gates g,o
            float hv[4] = {ha.x, ha.y, ha.z, ha.w};
#pragma unroll
            for (int ib = 0; ib < 4; ib++) {
                ull h2 = splat2(hv[ib]);
                acc[ib][0] = ffma2(h2, w01, acc[ib][0]);
                acc[ib][1] = ffma2(h2, w23, acc[ib][1]);
            }
        }
#pragma unroll
        for (int ib = 0; ib < 4; ib++) {
            int b = bg * 4 + ib;
            pdst[(size_t)b * 512 + hc1] =
                make_float4(lo2(acc[ib][0]), hi2(acc[ib][0]), lo2(acc[ib][1]), hi2(acc[ib][1]));
        }
        grid_barrier();

        // ------- phase 2: reduce + activations + state update -------
        const int t = dir2 ? (TT - 1 - s) : s;
        const float4* p4 = (const float4*)g_part;
        float4 sum = make_float4(0.f, 0.f, 0.f, 0.f);
#pragma unroll
        for (int k4 = 0; k4 < 4; k4++) {
            float4 v = __ldcg(&p4[((size_t)(k4 * 2 + dir2) * 32 + b2) * 512 + hc2]);
            sum.x += v.x; sum.y += v.y; sum.z += v.z; sum.w += v.w;
        }
        const float* xgb = g_xg + ((size_t)dir2 * TBM + (size_t)t * BB + b2) * G4 + hc2;
        float gi = sum.x + __ldg(xgb);
        float gf = sum.y + __ldg(xgb + HH);
        float gg = sum.z + __ldg(xgb + 2 * HH);
        float go = sum.w + __ldg(xgb + 3 * HH);

        c_reg = sigmoidf_(gf) * c_reg + sigmoidf_(gi) * tanhf(gg);
        h_reg = sigmoidf_(go) * tanhf(c_reg);

        g_hmT[dir2 * 16384 + hc2 * 32 + b2] = h_reg * mh;
        if (layer == 0)
            g_y[(size_t)dir2 * TBM * HH + ((size_t)t * BB + b2) * HH + hc2] = h_reg;
        else
            out[((size_t)b2 * TT + t) * (2 * HH) + dir2 * HH + hc2] = h_reg;

        grid_barrier();
    }

    // final hn / cn from registers
    out[OUT_HN + (size_t)layer * 32768 + gid] = h_reg;
    out[OUT_CN + (size_t)layer * 32768 + gid] = c_reg;
}

// ---------------- launcher ----------------
extern "C" void kernel_launch(void* const* d_in, const int* in_sizes, int n_in,
                              void* d_out, int out_size) {
    (void)in_sizes; (void)n_in; (void)out_size;
    const float* x       = (const float*)d_in[0];
    const float* mask_x  = (const float*)d_in[1];
    const float* mask_out= (const float*)d_in[2];
    const float* mask_h  = (const float*)d_in[3];
    const float* w_ih_l0 = (const float*)d_in[4];
    const float* w_hh_l0 = (const float*)d_in[5];
    const float* b_l0    = (const float*)d_in[6];
    const float* w_ih_l1 = (const float*)d_in[7];
    const float* w_hh_l1 = (const float*)d_in[8];
    const float* b_l1    = (const float*)d_in[9];
    float* out = (float*)d_out;

    float *p_xm = nullptr, *p_xg = nullptr;
    cudaGetSymbolAddress((void**)&p_xm, g_xm);
    cudaGetSymbolAddress((void**)&p_xg, g_xg);

    const int scan_smem = (32 * SW_STRIDE + 1024) * 16;   // 83968 bytes
    cudaFuncSetAttribute(lstm_scan, cudaFuncAttributeMaxDynamicSharedMemorySize, scan_smem);

    k_build_whhT<<<4194304 / 256, 256>>>(w_hh_l0, w_hh_l1);
    k_mask_in0<<<8388608 / 256, 256>>>(x, mask_x);

    for (int dir = 0; dir < 2; dir++)
        gemm_nt_bias<<<dim3(16, 128), 256>>>(p_xm, w_ih_l0 + (size_t)dir * G4 * DD,
                                             b_l0 + dir * G4,
                                             p_xg + (size_t)dir * TBM * G4, DD);

    lstm_scan<<<NBLK, 256, scan_smem>>>(0, out, mask_h);

    k_build_in1<<<16777216 / 256, 256>>>(mask_out);
    for (int dir = 0; dir < 2; dir++)
        gemm_nt_bias<<<dim3(16, 128), 256>>>(p_xm, w_ih_l1 + (size_t)dir * G4 * (2 * HH),
                                             b_l1 + dir * G4,
                                             p_xg + (size_t)dir * TBM * G4, 2 * HH);

    lstm_scan<<<NBLK, 256, scan_smem>>>(1, out, mask_h);
}

// round 5
// speedup vs baseline: 1.3133x; 1.1059x over previous
#include <cuda_runtime.h>
#include <math.h>

// Problem constants
#define DIRS 2
#define BB   32
#define TT   512
#define DD   512
#define HH   512
#define G4   2048            // 4*H
#define TBM  16384           // T*B
#define NBLK 128             // persistent scan grid (1 block/SM, all co-resident)

static const size_t OUT_HN = (size_t)BB * TT * 2 * HH;   // 16777216
static const size_t OUT_CN = OUT_HN + 4ULL * BB * HH;    // 16842752

typedef unsigned long long ull;

// ---------------- scratch (static device globals; no allocation) ----------------
__device__ __align__(16) float g_xm[(size_t)TBM * 1024];
__device__ __align__(16) float g_xg[(size_t)DIRS * TBM * G4];
__device__ __align__(16) float g_y[(size_t)DIRS * TBM * HH];
__device__ __align__(16) float g_whhT[(size_t)2 * DIRS * HH * HH * 4]; // [layer][dir][hc][k][gate]
__device__ __align__(16) float g_hmT[DIRS * HH * BB];                  // [dir][k][b]

// grid barrier state
__device__ unsigned g_bar_count = 0;
__device__ unsigned g_bar_gen = 0;

// ---------------- f32x2 helpers ----------------
__device__ __forceinline__ ull pack2(float x, float y) {
    ull r;
    asm("mov.b64 %0, {%1, %2};" : "=l"(r) : "r"(__float_as_uint(x)), "r"(__float_as_uint(y)));
    return r;
}
__device__ __forceinline__ ull splat2(float x) {
    ull r; unsigned u = __float_as_uint(x);
    asm("mov.b64 %0, {%1, %1};" : "=l"(r) : "r"(u));
    return r;
}
__device__ __forceinline__ ull ffma2(ull a, ull b, ull c) {
    ull d;
    asm("fma.rn.f32x2 %0, %1, %2, %3;" : "=l"(d) : "l"(a), "l"(b), "l"(c));
    return d;
}
__device__ __forceinline__ float lo2(ull v) { return __uint_as_float((unsigned)(v & 0xffffffffu)); }
__device__ __forceinline__ float hi2(ull v) { return __uint_as_float((unsigned)(v >> 32)); }
__device__ __forceinline__ float sigmoidf_(float x) { return 1.0f / (1.0f + expf(-x)); }

// sense-reversing grid barrier (one per timestep)
__device__ __forceinline__ void grid_barrier() {
    __syncthreads();
    if (threadIdx.x == 0) {
        __threadfence();                          // release this block's stores
        volatile unsigned* genp = &g_bar_gen;
        unsigned old = *genp;
        unsigned t = atomicAdd(&g_bar_count, 1u);
        if (t == NBLK - 1) {
            g_bar_count = 0;
            __threadfence();
            g_bar_gen = old + 1;
        } else {
            while (*genp == old) {}
        }
        __threadfence();                          // acquire
    }
    __syncthreads();
}

// ---------------- prep kernels ----------------
__global__ void k_mask_in0(const float* __restrict__ x, const float* __restrict__ mask_x) {
    int gid = blockIdx.x * 256 + threadIdx.x;          // < 8388608
    int k = gid & 511; int b = (gid >> 9) & 31; int t = gid >> 14;
    g_xm[gid] = x[((size_t)b * TT + t) * DD + k] * mask_x[b * 512 + k];
}

__global__ void k_build_whhT(const float* __restrict__ w0, const float* __restrict__ w1) {
    int gid = blockIdx.x * 256 + threadIdx.x;          // < 4194304
    int g = gid & 3; int k = (gid >> 2) & 511; int hc = (gid >> 11) & 511;
    int dir = (gid >> 20) & 1; int layer = (gid >> 21) & 1;
    const float* w = layer ? w1 : w0;
    g_whhT[gid] = w[(size_t)dir * G4 * HH + (size_t)(g * HH + hc) * HH + k];
}

__global__ void k_build_in1(const float* __restrict__ mask_out) {
    int gid = blockIdx.x * 256 + threadIdx.x;          // < 16777216
    int j = gid & 1023; int b = (gid >> 10) & 31; int t = gid >> 15;
    int dir = j >> 9; int hc = j & 511;
    g_xm[gid] = g_y[(size_t)dir * TBM * HH + (size_t)(t * BB + b) * HH + hc] * mask_out[b * 1024 + j];
}

// ---------------- input-projection GEMM: C[M,2048] = A[M,K] * W[2048,K]^T + bias ----------------
__global__ void __launch_bounds__(256, 2) gemm_nt_bias(
    const float* __restrict__ A, const float* __restrict__ W,
    const float* __restrict__ bias, float* __restrict__ C, int K)
{
    __shared__ __align__(16) float As[8][128];
    __shared__ __align__(16) float Ws[8][128];
    const int tid = threadIdx.x;
    const int m0 = blockIdx.y * 128;
    const int n0 = blockIdx.x * 128;
    const int lrow = tid >> 1;
    const int lseg = (tid & 1) * 4;
    const float* Ap = A + (size_t)(m0 + lrow) * K + lseg;
    const float* Wp = W + (size_t)(n0 + lrow) * K + lseg;
    const int ty = tid >> 4, tx = tid & 15;

    ull acc[8][4];
#pragma unroll
    for (int i = 0; i < 8; i++) { acc[i][0] = 0; acc[i][1] = 0; acc[i][2] = 0; acc[i][3] = 0; }

    for (int k0 = 0; k0 < K; k0 += 8) {
        float4 av = *(const float4*)(Ap + k0);
        float4 wv = *(const float4*)(Wp + k0);
        __syncthreads();
        As[lseg + 0][lrow] = av.x; As[lseg + 1][lrow] = av.y;
        As[lseg + 2][lrow] = av.z; As[lseg + 3][lrow] = av.w;
        Ws[lseg + 0][lrow] = wv.x; Ws[lseg + 1][lrow] = wv.y;
        Ws[lseg + 2][lrow] = wv.z; Ws[lseg + 3][lrow] = wv.w;
        __syncthreads();
#pragma unroll
        for (int kk = 0; kk < 8; kk++) {
            float4 a0 = *(const float4*)&As[kk][ty * 8];
            float4 a1 = *(const float4*)&As[kk][ty * 8 + 4];
            float4 b0 = *(const float4*)&Ws[kk][tx * 8];
            float4 b1 = *(const float4*)&Ws[kk][tx * 8 + 4];
            ull bp0 = pack2(b0.x, b0.y), bp1 = pack2(b0.z, b0.w);
            ull bp2 = pack2(b1.x, b1.y), bp3 = pack2(b1.z, b1.w);
            float aa[8] = {a0.x, a0.y, a0.z, a0.w, a1.x, a1.y, a1.z, a1.w};
#pragma unroll
            for (int i = 0; i < 8; i++) {
                ull a2 = splat2(aa[i]);
                acc[i][0] = ffma2(a2, bp0, acc[i][0]);
                acc[i][1] = ffma2(a2, bp1, acc[i][1]);
                acc[i][2] = ffma2(a2, bp2, acc[i][2]);
                acc[i][3] = ffma2(a2, bp3, acc[i][3]);
            }
        }
    }
    float bs[8];
#pragma unroll
    for (int j = 0; j < 8; j++) bs[j] = bias[n0 + tx * 8 + j];
#pragma unroll
    for (int i = 0; i < 8; i++) {
        float* Crow = C + (size_t)(m0 + ty * 8 + i) * G4 + n0 + tx * 8;
        float4 v0 = make_float4(lo2(acc[i][0]) + bs[0], hi2(acc[i][0]) + bs[1],
                                lo2(acc[i][1]) + bs[2], hi2(acc[i][1]) + bs[3]);
        float4 v1 = make_float4(lo2(acc[i][2]) + bs[4], hi2(acc[i][2]) + bs[5],
                                lo2(acc[i][3]) + bs[6], hi2(acc[i][3]) + bs[7]);
        *(float4*)(Crow) = v0;
        *(float4*)(Crow + 4) = v1;
    }
}

// ---------------- fused persistent scan: ONE grid barrier per timestep ----------------
// Block = (dir, jt in 0..63): owns hc tile [jt*8, jt*8+8), all 4 gates, all 32 b, full K=512.
// Thread (kc16, hcp4, bq4): tile 2hc x 4g x 8b over 32 k. In-block kc-reduction via SMEM.
// Phase2 (pointwise LSTM) in-block: thread (hc_local8, b32); c/h in registers across steps.
#define SW_STRIDE 514   // float4 per hc weight row (512 + pad, stride % 8 == 2)
#define RED_STRIDE 33   // float4 per (kc,hc) reduction row (32 + pad)

__global__ void __launch_bounds__(256, 1) lstm_scan(int layer, float* __restrict__ out,
                                                    const float* __restrict__ mask_h) {
    extern __shared__ __align__(16) float4 smem4[];
    float4* sw4   = smem4;                       // 8 * 514  = 4112 float4 (65792 B)
    float4* s_hm4 = smem4 + 8 * SW_STRIDE;       // 4096 float4 (65536 B)
    float4* red4  = s_hm4 + 4096;                // 16*8*33 = 4224 float4 (67584 B)

    const int bx = blockIdx.x;
    const int tid = threadIdx.x;
    const int dirb = bx >> 6;                    // direction
    const int jt = bx & 63;                      // hc tile of 8

    // ---- phase1 thread identity ----
    const int kc  = tid >> 4;                    // 0..15 : k chunk of 32
    const int hcp = (tid >> 2) & 3;              // hc pair (2 hc)
    const int bq  = tid & 3;                     // 8-b group

    const float4* whhT4 = (const float4*)g_whhT;
    const float4* hsrc = (const float4*)g_hmT + dirb * 4096;

    // load this block's weight slice into SMEM once (8 hc rows x 512 k, 4 gates per float4)
    {
        const size_t rowbase = ((size_t)(layer * 2 + dirb) * 512 + jt * 8) * 512;
        for (int idx = tid; idx < 4096; idx += 256) {
            int r = idx >> 9, k = idx & 511;
            sw4[r * SW_STRIDE + k] = whhT4[rowbase + (size_t)r * 512 + k];
        }
    }

    // ---- phase2 thread identity ----
    const int hc_local = tid >> 5;               // 0..7
    const int b2 = tid & 31;                     // batch
    const int hcg = jt * 8 + hc_local;           // global hidden index
    const float mh = mask_h[(size_t)layer * 16384 + dirb * 0 + b2 * 512 + hcg]; // mask_h[layer][b][h]
    float h_reg = 0.f, c_reg = 0.f;

    // init hmT(t=-1) = 0 (each element written exactly once across the grid)
    g_hmT[dirb * 16384 + hcg * 32 + b2] = 0.f;
    grid_barrier();

    const float4* wrow0 = sw4 + (hcp * 2) * SW_STRIDE + kc * 32;
    const float4* wrow1 = wrow0 + SW_STRIDE;
    const float4* hrow  = s_hm4 + (size_t)kc * 32 * 8 + bq * 2;

    for (int s = 0; s < TT; s++) {
        const int t = dirb ? (TT - 1 - s) : s;

        // prefetch xg gates for this thread's phase2 (hidden under the GEMM)
        const float* xgb = g_xg + ((size_t)dirb * TBM + (size_t)t * BB + b2) * G4 + hcg;
        float xi = __ldcg(xgb);
        float xf = __ldcg(xgb + HH);
        float xg_ = __ldcg(xgb + 2 * HH);
        float xo = __ldcg(xgb + 3 * HH);

        // stage h*mask (previous step, all blocks) into SMEM
#pragma unroll
        for (int i = 0; i < 16; i++) s_hm4[tid + i * 256] = __ldcg(hsrc + tid + i * 256);
        __syncthreads();

        // ------- recurrent GEMM over this thread's 32-k chunk -------
        ull a0[8][2], a1[8][2];
#pragma unroll
        for (int i = 0; i < 8; i++) { a0[i][0] = 0; a0[i][1] = 0; a1[i][0] = 0; a1[i][1] = 0; }

#pragma unroll 4
        for (int kk = 0; kk < 32; kk++) {
            float4 w0 = wrow0[kk];
            float4 w1 = wrow1[kk];
            float4 hA = hrow[kk * 8];
            float4 hB = hrow[kk * 8 + 1];
            ull w0if = pack2(w0.x, w0.y), w0go = pack2(w0.z, w0.w);
            ull w1if = pack2(w1.x, w1.y), w1go = pack2(w1.z, w1.w);
            float hv[8] = {hA.x, hA.y, hA.z, hA.w, hB.x, hB.y, hB.z, hB.w};
#pragma unroll
            for (int ib = 0; ib < 8; ib++) {
                ull h2 = splat2(hv[ib]);
                a0[ib][0] = ffma2(h2, w0if, a0[ib][0]);
                a0[ib][1] = ffma2(h2, w0go, a0[ib][1]);
                a1[ib][0] = ffma2(h2, w1if, a1[ib][0]);
                a1[ib][1] = ffma2(h2, w1go, a1[ib][1]);
            }
        }

        // ------- store partials to padded SMEM reduction buffer -------
        {
            float4* r0 = red4 + (size_t)(kc * 8 + hcp * 2) * RED_STRIDE + bq * 8;
            float4* r1 = r0 + RED_STRIDE;
#pragma unroll
            for (int ib = 0; ib < 8; ib++) {
                r0[ib] = make_float4(lo2(a0[ib][0]), hi2(a0[ib][0]), lo2(a0[ib][1]), hi2(a0[ib][1]));
                r1[ib] = make_float4(lo2(a1[ib][0]), hi2(a1[ib][0]), lo2(a1[ib][1]), hi2(a1[ib][1]));
            }
        }
        __syncthreads();

        // ------- in-block reduce + pointwise LSTM -------
        float gi = xi, gf = xf, gg = xg_, go = xo;
#pragma unroll
        for (int k16 = 0; k16 < 16; k16++) {
            float4 v = red4[(size_t)(k16 * 8 + hc_local) * RED_STRIDE + b2];
            gi += v.x; gf += v.y; gg += v.z; go += v.w;
        }
        c_reg = sigmoidf_(gf) * c_reg + sigmoidf_(gi) * tanhf(gg);
        h_reg = sigmoidf_(go) * tanhf(c_reg);

        g_hmT[dirb * 16384 + hcg * 32 + b2] = h_reg * mh;
        if (layer == 0)
            g_y[(size_t)dirb * TBM * HH + ((size_t)t * BB + b2) * HH + hcg] = h_reg;
        else
            out[((size_t)b2 * TT + t) * (2 * HH) + dirb * HH + hcg] = h_reg;

        grid_barrier();
    }

    // final hn / cn from registers: [layer*2+dir][b][h]
    out[OUT_HN + (size_t)layer * 32768 + dirb * 16384 + b2 * 512 + hcg] = h_reg;
    out[OUT_CN + (size_t)layer * 32768 + dirb * 16384 + b2 * 512 + hcg] = c_reg;
}

// ---------------- launcher ----------------
extern "C" void kernel_launch(void* const* d_in, const int* in_sizes, int n_in,
                              void* d_out, int out_size) {
    (void)in_sizes; (void)n_in; (void)out_size;
    const float* x       = (const float*)d_in[0];
    const float* mask_x  = (const float*)d_in[1];
    const float* mask_out= (const float*)d_in[2];
    const float* mask_h  = (const float*)d_in[3];
    const float* w_ih_l0 = (const float*)d_in[4];
    const float* w_hh_l0 = (const float*)d_in[5];
    const float* b_l0    = (const float*)d_in[6];
    const float* w_ih_l1 = (const float*)d_in[7];
    const float* w_hh_l1 = (const float*)d_in[8];
    const float* b_l1    = (const float*)d_in[9];
    float* out = (float*)d_out;

    float *p_xm = nullptr, *p_xg = nullptr;
    cudaGetSymbolAddress((void**)&p_xm, g_xm);
    cudaGetSymbolAddress((void**)&p_xg, g_xg);

    const int scan_smem = (8 * SW_STRIDE + 4096 + 16 * 8 * RED_STRIDE) * 16;  // 198912 B
    cudaFuncSetAttribute(lstm_scan, cudaFuncAttributeMaxDynamicSharedMemorySize, scan_smem);

    k_build_whhT<<<4194304 / 256, 256>>>(w_hh_l0, w_hh_l1);
    k_mask_in0<<<8388608 / 256, 256>>>(x, mask_x);

    for (int dir = 0; dir < 2; dir++)
        gemm_nt_bias<<<dim3(16, 128), 256>>>(p_xm, w_ih_l0 + (size_t)dir * G4 * DD,
                                             b_l0 + dir * G4,
                                             p_xg + (size_t)dir * TBM * G4, DD);

    lstm_scan<<<NBLK, 256, scan_smem>>>(0, out, mask_h);

    k_build_in1<<<16777216 / 256, 256>>>(mask_out);
    for (int dir = 0; dir < 2; dir++)
        gemm_nt_bias<<<dim3(16, 128), 256>>>(p_xm, w_ih_l1 + (size_t)dir * G4 * (2 * HH),
                                             b_l1 + dir * G4,
                                             p_xg + (size_t)dir * TBM * G4, 2 * HH);

    lstm_scan<<<NBLK, 256, scan_smem>>>(1, out, mask_h);
}

// round 6
// speedup vs baseline: 1.3602x; 1.0358x over previous
#include <cuda_runtime.h>
#include <math.h>

// Problem constants
#define DIRS 2
#define BB   32
#define TT   512
#define DD   512
#define HH   512
#define G4   2048            // 4*H
#define TBM  16384           // T*B
#define NBLK 128             // persistent scan grid (1 block/SM, all co-resident)

static const size_t OUT_HN = (size_t)BB * TT * 2 * HH;   // 16777216
static const size_t OUT_CN = OUT_HN + 4ULL * BB * HH;    // 16842752

typedef unsigned long long ull;

// ---------------- scratch (static device globals; no allocation) ----------------
__device__ __align__(16) float g_xm[(size_t)TBM * 1024];
__device__ __align__(16) float g_xg[(size_t)DIRS * TBM * G4];
__device__ __align__(16) float g_y[(size_t)DIRS * TBM * HH];
__device__ __align__(16) float g_whhT[(size_t)2 * DIRS * HH * HH * 4]; // [layer][dir][hc][k][gate]
__device__ __align__(16) float g_hmT[2][DIRS * HH * BB];               // ping-pong [par][dir][k][b]
__device__ unsigned g_flags[DIRS * 64 * 32];                           // flag per (dir,jt), 128B apart

// init-barrier state (atomic barrier used once per scan launch)
__device__ unsigned g_bar_count = 0;
__device__ unsigned g_bar_gen = 0;

// ---------------- f32x2 helpers ----------------
__device__ __forceinline__ ull pack2(float x, float y) {
    ull r;
    asm("mov.b64 %0, {%1, %2};" : "=l"(r) : "r"(__float_as_uint(x)), "r"(__float_as_uint(y)));
    return r;
}
__device__ __forceinline__ ull splat2(float x) {
    ull r; unsigned u = __float_as_uint(x);
    asm("mov.b64 %0, {%1, %1};" : "=l"(r) : "r"(u));
    return r;
}
__device__ __forceinline__ ull ffma2(ull a, ull b, ull c) {
    ull d;
    asm("fma.rn.f32x2 %0, %1, %2, %3;" : "=l"(d) : "l"(a), "l"(b), "l"(c));
    return d;
}
__device__ __forceinline__ float lo2(ull v) { return __uint_as_float((unsigned)(v & 0xffffffffu)); }
__device__ __forceinline__ float hi2(ull v) { return __uint_as_float((unsigned)(v >> 32)); }
__device__ __forceinline__ float sigmoidf_(float x) { return 1.0f / (1.0f + expf(-x)); }

// atomic sense-reversing grid barrier: used ONCE per scan launch (init only)
__device__ __forceinline__ void grid_barrier() {
    __syncthreads();
    if (threadIdx.x == 0) {
        __threadfence();
        volatile unsigned* genp = &g_bar_gen;
        unsigned old = *genp;
        unsigned t = atomicAdd(&g_bar_count, 1u);
        if (t == NBLK - 1) {
            g_bar_count = 0;
            __threadfence();
            g_bar_gen = old + 1;
        } else {
            while (*genp == old) {}
        }
        __threadfence();
    }
    __syncthreads();
}

// ---------------- prep kernels ----------------
__global__ void k_mask_in0(const float* __restrict__ x, const float* __restrict__ mask_x) {
    int gid = blockIdx.x * 256 + threadIdx.x;          // < 8388608
    int k = gid & 511; int b = (gid >> 9) & 31; int t = gid >> 14;
    g_xm[gid] = x[((size_t)b * TT + t) * DD + k] * mask_x[b * 512 + k];
}

__global__ void k_build_whhT(const float* __restrict__ w0, const float* __restrict__ w1) {
    int gid = blockIdx.x * 256 + threadIdx.x;          // < 4194304
    int g = gid & 3; int k = (gid >> 2) & 511; int hc = (gid >> 11) & 511;
    int dir = (gid >> 20) & 1; int layer = (gid >> 21) & 1;
    const float* w = layer ? w1 : w0;
    g_whhT[gid] = w[(size_t)dir * G4 * HH + (size_t)(g * HH + hc) * HH + k];
}

__global__ void k_build_in1(const float* __restrict__ mask_out) {
    int gid = blockIdx.x * 256 + threadIdx.x;          // < 16777216
    int j = gid & 1023; int b = (gid >> 10) & 31; int t = gid >> 15;
    int dir = j >> 9; int hc = j & 511;
    g_xm[gid] = g_y[(size_t)dir * TBM * HH + (size_t)(t * BB + b) * HH + hc] * mask_out[b * 1024 + j];
}

// ---------------- input-projection GEMM: C[M,2048] = A[M,K] * W[2048,K]^T + bias ----------------
__global__ void __launch_bounds__(256, 2) gemm_nt_bias(
    const float* __restrict__ A, const float* __restrict__ W,
    const float* __restrict__ bias, float* __restrict__ C, int K)
{
    __shared__ __align__(16) float As[8][128];
    __shared__ __align__(16) float Ws[8][128];
    const int tid = threadIdx.x;
    const int m0 = blockIdx.y * 128;
    const int n0 = blockIdx.x * 128;
    const int lrow = tid >> 1;
    const int lseg = (tid & 1) * 4;
    const float* Ap = A + (size_t)(m0 + lrow) * K + lseg;
    const float* Wp = W + (size_t)(n0 + lrow) * K + lseg;
    const int ty = tid >> 4, tx = tid & 15;

    ull acc[8][4];
#pragma unroll
    for (int i = 0; i < 8; i++) { acc[i][0] = 0; acc[i][1] = 0; acc[i][2] = 0; acc[i][3] = 0; }

    for (int k0 = 0; k0 < K; k0 += 8) {
        float4 av = *(const float4*)(Ap + k0);
        float4 wv = *(const float4*)(Wp + k0);
        __syncthreads();
        As[lseg + 0][lrow] = av.x; As[lseg + 1][lrow] = av.y;
        As[lseg + 2][lrow] = av.z; As[lseg + 3][lrow] = av.w;
        Ws[lseg + 0][lrow] = wv.x; Ws[lseg + 1][lrow] = wv.y;
        Ws[lseg + 2][lrow] = wv.z; Ws[lseg + 3][lrow] = wv.w;
        __syncthreads();
#pragma unroll
        for (int kk = 0; kk < 8; kk++) {
            float4 a0 = *(const float4*)&As[kk][ty * 8];
            float4 a1 = *(const float4*)&As[kk][ty * 8 + 4];
            float4 b0 = *(const float4*)&Ws[kk][tx * 8];
            float4 b1 = *(const float4*)&Ws[kk][tx * 8 + 4];
            ull bp0 = pack2(b0.x, b0.y), bp1 = pack2(b0.z, b0.w);
            ull bp2 = pack2(b1.x, b1.y), bp3 = pack2(b1.z, b1.w);
            float aa[8] = {a0.x, a0.y, a0.z, a0.w, a1.x, a1.y, a1.z, a1.w};
#pragma unroll
            for (int i = 0; i < 8; i++) {
                ull a2 = splat2(aa[i]);
                acc[i][0] = ffma2(a2, bp0, acc[i][0]);
                acc[i][1] = ffma2(a2, bp1, acc[i][1]);
                acc[i][2] = ffma2(a2, bp2, acc[i][2]);
                acc[i][3] = ffma2(a2, bp3, acc[i][3]);
            }
        }
    }
    float bs[8];
#pragma unroll
    for (int j = 0; j < 8; j++) bs[j] = bias[n0 + tx * 8 + j];
#pragma unroll
    for (int i = 0; i < 8; i++) {
        float* Crow = C + (size_t)(m0 + ty * 8 + i) * G4 + n0 + tx * 8;
        float4 v0 = make_float4(lo2(acc[i][0]) + bs[0], hi2(acc[i][0]) + bs[1],
                                lo2(acc[i][1]) + bs[2], hi2(acc[i][1]) + bs[3]);
        float4 v1 = make_float4(lo2(acc[i][2]) + bs[4], hi2(acc[i][2]) + bs[5],
                                lo2(acc[i][3]) + bs[6], hi2(acc[i][3]) + bs[7]);
        *(float4*)(Crow) = v0;
        *(float4*)(Crow + 4) = v1;
    }
}

// ---------------- fused persistent scan, flag-based per-dir sync ----------------
// Block (dir, jt): hc tile [jt*8, jt*8+8), 4 gates, 32 b, full K=512.
// Thread (kc16, hcp4, bq4): 2hc x 4g x 8b over own 32-k chunk; in-block SMEM reduce.
// h ping-pongs between g_hmT[0]/g_hmT[1]; per-(dir,jt) monotonic flags synchronize steps.
#define SW_STRIDE 514   // float4 per hc weight row (512 + pad)
#define RED_STRIDE 33   // float4 per (kc,hc) reduction row (32 + pad)

__global__ void __launch_bounds__(256, 1) lstm_scan(int layer, float* __restrict__ out,
                                                    const float* __restrict__ mask_h) {
    extern __shared__ __align__(16) float4 smem4[];
    float4* sw4   = smem4;                       // 8 * 514  float4
    float4* s_hm4 = smem4 + 8 * SW_STRIDE;       // 4096 float4
    float4* red4  = s_hm4 + 4096;                // 128 * 33 float4

    const int bx = blockIdx.x;
    const int tid = threadIdx.x;
    const int dirb = bx >> 6;
    const int jt = bx & 63;

    // phase1 thread identity
    const int kc  = tid >> 4;                    // 0..15 : 32-k chunk
    const int hcp = (tid >> 2) & 3;              // hc pair
    const int bq  = tid & 3;                     // 8-b group
    const int sub = tid & 15;                    // lane within kc group

    // load weight slice into SMEM once
    {
        const float4* whhT4 = (const float4*)g_whhT;
        const size_t rowbase = ((size_t)(layer * 2 + dirb) * 512 + jt * 8) * 512;
        for (int idx = tid; idx < 4096; idx += 256) {
            int r = idx >> 9, k = idx & 511;
            sw4[r * SW_STRIDE + k] = whhT4[rowbase + (size_t)r * 512 + k];
        }
    }

    // phase2 thread identity
    const int hc_local = tid >> 5;
    const int b2 = tid & 31;
    const int hcg = jt * 8 + hc_local;
    const float mh = mask_h[(size_t)layer * 16384 + b2 * 512 + hcg];
    float h_reg = 0.f, c_reg = 0.f;

    // reset own flag + init read buffer h(-1)=0; single atomic barrier makes it visible
    if (tid == 0) *(volatile unsigned*)&g_flags[(dirb * 64 + jt) * 32] = 0u;
    g_hmT[1][dirb * 16384 + hcg * 32 + b2] = 0.f;
    grid_barrier();

    volatile unsigned* myflags = (volatile unsigned*)(g_flags + dirb * 64 * 32);
    const float4* wrow0 = sw4 + (hcp * 2) * SW_STRIDE + kc * 32;
    const float4* wrow1 = wrow0 + SW_STRIDE;
    const float4* hrow  = s_hm4 + kc * 256 + bq * 2;
    const int lane = tid & 31;

    for (int s = 0; s < TT; s++) {
        const int t = dirb ? (TT - 1 - s) : s;

        // prefetch xg gates (DRAM; consumed post-GEMM, hidden under wait+GEMM)
        const float* xgb = g_xg + ((size_t)dirb * TBM + (size_t)t * BB + b2) * G4 + hcg;
        float xi = __ldcg(xgb);
        float xf = __ldcg(xgb + HH);
        float xg_ = __ldcg(xgb + 2 * HH);
        float xo = __ldcg(xgb + 3 * HH);

        // wait for all same-dir producers of h(s-1): every warp polls independently
        if (s > 0) {
            unsigned tgt = (unsigned)s;
            while (myflags[lane * 32] < tgt || myflags[(lane + 32) * 32] < tgt) {}
        }
        __syncwarp();

        // stage own kc region of h(s-1) (only this half-warp reads it)
        const float4* hb = (const float4*)(g_hmT[(s + 1) & 1]) + dirb * 4096 + kc * 256;
#pragma unroll
        for (int i = 0; i < 16; i++)
            s_hm4[kc * 256 + i * 16 + sub] = __ldcg(hb + i * 16 + sub);
        __syncwarp();

        // recurrent GEMM over this thread's 32-k chunk
        ull a0[8][2], a1[8][2];
#pragma unroll
        for (int i = 0; i < 8; i++) { a0[i][0] = 0; a0[i][1] = 0; a1[i][0] = 0; a1[i][1] = 0; }

#pragma unroll 4
        for (int kk = 0; kk < 32; kk++) {
            ulonglong2 w0 = *(const ulonglong2*)(wrow0 + kk);   // .x = gates i,f ; .y = g,o
            ulonglong2 w1 = *(const ulonglong2*)(wrow1 + kk);
            float4 hA = hrow[kk * 8];
            float4 hB = hrow[kk * 8 + 1];
            float hv[8] = {hA.x, hA.y, hA.z, hA.w, hB.x, hB.y, hB.z, hB.w};
#pragma unroll
            for (int ib = 0; ib < 8; ib++) {
                ull h2 = splat2(hv[ib]);
                a0[ib][0] = ffma2(h2, w0.x, a0[ib][0]);
                a0[ib][1] = ffma2(h2, w0.y, a0[ib][1]);
                a1[ib][0] = ffma2(h2, w1.x, a1[ib][0]);
                a1[ib][1] = ffma2(h2, w1.y, a1[ib][1]);
            }
        }

        // partials -> padded SMEM reduction buffer
        {
            float4* r0 = red4 + (size_t)(kc * 8 + hcp * 2) * RED_STRIDE + bq * 8;
            float4* r1 = r0 + RED_STRIDE;
#pragma unroll
            for (int ib = 0; ib < 8; ib++) {
                r0[ib] = make_float4(lo2(a0[ib][0]), hi2(a0[ib][0]), lo2(a0[ib][1]), hi2(a0[ib][1]));
                r1[ib] = make_float4(lo2(a1[ib][0]), hi2(a1[ib][0]), lo2(a1[ib][1]), hi2(a1[ib][1]));
            }
        }
        __syncthreads();

        // in-block reduce + pointwise LSTM
        float gi = xi, gf = xf, gg = xg_, go = xo;
#pragma unroll
        for (int k16 = 0; k16 < 16; k16++) {
            float4 v = red4[(size_t)(k16 * 8 + hc_local) * RED_STRIDE + b2];
            gi += v.x; gf += v.y; gg += v.z; go += v.w;
        }
        c_reg = sigmoidf_(gf) * c_reg + sigmoidf_(gi) * tanhf(gg);
        h_reg = sigmoidf_(go) * tanhf(c_reg);

        __stcg(&g_hmT[s & 1][dirb * 16384 + hcg * 32 + b2], h_reg * mh);
        if (layer == 0)
            g_y[(size_t)dirb * TBM * HH + ((size_t)t * BB + b2) * HH + hcg] = h_reg;
        else
            out[((size_t)b2 * TT + t) * (2 * HH) + dirb * HH + hcg] = h_reg;

        __threadfence();          // release this thread's h store before the flag
        __syncthreads();          // all threads of block released
        if (tid == 0) myflags[jt * 32] = (unsigned)(s + 1);
    }

    // final hn / cn from registers: [layer*2+dir][b][h]
    out[OUT_HN + (size_t)layer * 32768 + dirb * 16384 + b2 * 512 + hcg] = h_reg;
    out[OUT_CN + (size_t)layer * 32768 + dirb * 16384 + b2 * 512 + hcg] = c_reg;
}

// ---------------- launcher ----------------
extern "C" void kernel_launch(void* const* d_in, const int* in_sizes, int n_in,
                              void* d_out, int out_size) {
    (void)in_sizes; (void)n_in; (void)out_size;
    const float* x       = (const float*)d_in[0];
    const float* mask_x  = (const float*)d_in[1];
    const float* mask_out= (const float*)d_in[2];
    const float* mask_h  = (const float*)d_in[3];
    const float* w_ih_l0 = (const float*)d_in[4];
    const float* w_hh_l0 = (const float*)d_in[5];
    const float* b_l0    = (const float*)d_in[6];
    const float* w_ih_l1 = (const float*)d_in[7];
    const float* w_hh_l1 = (const float*)d_in[8];
    const float* b_l1    = (const float*)d_in[9];
    float* out = (float*)d_out;

    float *p_xm = nullptr, *p_xg = nullptr;
    cudaGetSymbolAddress((void**)&p_xm, g_xm);
    cudaGetSymbolAddress((void**)&p_xg, g_xg);

    const int scan_smem = (8 * SW_STRIDE + 4096 + 128 * RED_STRIDE) * 16;  // 198912 B
    cudaFuncSetAttribute(lstm_scan, cudaFuncAttributeMaxDynamicSharedMemorySize, scan_smem);

    k_build_whhT<<<4194304 / 256, 256>>>(w_hh_l0, w_hh_l1);
    k_mask_in0<<<8388608 / 256, 256>>>(x, mask_x);

    for (int dir = 0; dir < 2; dir++)
        gemm_nt_bias<<<dim3(16, 128), 256>>>(p_xm, w_ih_l0 + (size_t)dir * G4 * DD,
                                             b_l0 + dir * G4,
                                             p_xg + (size_t)dir * TBM * G4, DD);

    lstm_scan<<<NBLK, 256, scan_smem>>>(0, out, mask_h);

    k_build_in1<<<16777216 / 256, 256>>>(mask_out);
    for (int dir = 0; dir < 2; dir++)
        gemm_nt_bias<<<dim3(16, 128), 256>>>(p_xm, w_ih_l1 + (size_t)dir * G4 * (2 * HH),
                                             b_l1 + dir * G4,
                                             p_xg + (size_t)dir * TBM * G4, 2 * HH);

    lstm_scan<<<NBLK, 256, scan_smem>>>(1, out, mask_h);
}

// round 7
// speedup vs baseline: 1.3805x; 1.0149x over previous
#include <cuda_runtime.h>
#include <math.h>

// Problem constants
#define DIRS 2
#define BB   32
#define TT   512
#define DD   512
#define HH   512
#define G4   2048            // 4*H
#define TBM  16384           // T*B
#define NBLK 128             // persistent scan grid (1 block/SM, all co-resident)

static const size_t OUT_HN = (size_t)BB * TT * 2 * HH;   // 16777216
static const size_t OUT_CN = OUT_HN + 4ULL * BB * HH;    // 16842752

typedef unsigned long long ull;

// ---------------- scratch (static device globals; no allocation) ----------------
__device__ __align__(16) float g_xm[(size_t)TBM * 1024];
__device__ __align__(16) float g_xg[(size_t)DIRS * TBM * G4];
__device__ __align__(16) float g_y[(size_t)DIRS * TBM * HH];
__device__ __align__(16) float g_whhT[(size_t)2 * DIRS * HH * HH * 4]; // [layer][dir][hc][k][gate]
__device__ __align__(16) float g_hmT[2][DIRS * HH * BB];               // ping-pong [par][dir][k][b]
__device__ unsigned g_flags[DIRS * 64 * 32];                           // flag per (dir,jt), 128B apart

// init-barrier state (atomic barrier used once per scan launch)
__device__ unsigned g_bar_count = 0;
__device__ unsigned g_bar_gen = 0;

// ---------------- f32x2 helpers ----------------
__device__ __forceinline__ ull pack2(float x, float y) {
    ull r;
    asm("mov.b64 %0, {%1, %2};" : "=l"(r) : "r"(__float_as_uint(x)), "r"(__float_as_uint(y)));
    return r;
}
__device__ __forceinline__ ull splat2(float x) {
    ull r; unsigned u = __float_as_uint(x);
    asm("mov.b64 %0, {%1, %1};" : "=l"(r) : "r"(u));
    return r;
}
__device__ __forceinline__ ull ffma2(ull a, ull b, ull c) {
    ull d;
    asm("fma.rn.f32x2 %0, %1, %2, %3;" : "=l"(d) : "l"(a), "l"(b), "l"(c));
    return d;
}
__device__ __forceinline__ float lo2(ull v) { return __uint_as_float((unsigned)(v & 0xffffffffu)); }
__device__ __forceinline__ float hi2(ull v) { return __uint_as_float((unsigned)(v >> 32)); }

// NaN-safe fast activations (MUFU-based). |err| ~2ulp of exp, fine vs 1e-3 tol.
__device__ __forceinline__ float fast_sigmoid(float x) {
    return __fdividef(1.0f, 1.0f + __expf(-x));
}
__device__ __forceinline__ float fast_tanh(float x) {
    return 1.0f - __fdividef(2.0f, 1.0f + __expf(2.0f * x));   // no NaN for any finite x
}

// atomic sense-reversing grid barrier: used ONCE per scan launch (init only)
__device__ __forceinline__ void grid_barrier() {
    __syncthreads();
    if (threadIdx.x == 0) {
        __threadfence();
        volatile unsigned* genp = &g_bar_gen;
        unsigned old = *genp;
        unsigned t = atomicAdd(&g_bar_count, 1u);
        if (t == NBLK - 1) {
            g_bar_count = 0;
            __threadfence();
            g_bar_gen = old + 1;
        } else {
            while (*genp == old) {}
        }
        __threadfence();
    }
    __syncthreads();
}

// ---------------- prep kernels ----------------
// split into two launches (profiling shim: puts lstm_scan at launch #6 for ncu -s 5)
__global__ void k_mask_in0(const float* __restrict__ x, const float* __restrict__ mask_x,
                           int base) {
    int gid = base + blockIdx.x * 256 + threadIdx.x;   // < 8388608
    int k = gid & 511; int b = (gid >> 9) & 31; int t = gid >> 14;
    g_xm[gid] = x[((size_t)b * TT + t) * DD + k] * mask_x[b * 512 + k];
}

__global__ void k_build_whhT(const float* __restrict__ w0, const float* __restrict__ w1) {
    int gid = blockIdx.x * 256 + threadIdx.x;          // < 4194304
    int g = gid & 3; int k = (gid >> 2) & 511; int hc = (gid >> 11) & 511;
    int dir = (gid >> 20) & 1; int layer = (gid >> 21) & 1;
    const float* w = layer ? w1 : w0;
    g_whhT[gid] = w[(size_t)dir * G4 * HH + (size_t)(g * HH + hc) * HH + k];
}

__global__ void k_build_in1(const float* __restrict__ mask_out) {
    int gid = blockIdx.x * 256 + threadIdx.x;          // < 16777216
    int j = gid & 1023; int b = (gid >> 10) & 31; int t = gid >> 15;
    int dir = j >> 9; int hc = j & 511;
    g_xm[gid] = g_y[(size_t)dir * TBM * HH + (size_t)(t * BB + b) * HH + hc] * mask_out[b * 1024 + j];
}

// ---------------- input-projection GEMM: C[M,2048] = A[M,K] * W[2048,K]^T + bias ----------------
__global__ void __launch_bounds__(256, 2) gemm_nt_bias(
    const float* __restrict__ A, const float* __restrict__ W,
    const float* __restrict__ bias, float* __restrict__ C, int K)
{
    __shared__ __align__(16) float As[8][128];
    __shared__ __align__(16) float Ws[8][128];
    const int tid = threadIdx.x;
    const int m0 = blockIdx.y * 128;
    const int n0 = blockIdx.x * 128;
    const int lrow = tid >> 1;
    const int lseg = (tid & 1) * 4;
    const float* Ap = A + (size_t)(m0 + lrow) * K + lseg;
    const float* Wp = W + (size_t)(n0 + lrow) * K + lseg;
    const int ty = tid >> 4, tx = tid & 15;

    ull acc[8][4];
#pragma unroll
    for (int i = 0; i < 8; i++) { acc[i][0] = 0; acc[i][1] = 0; acc[i][2] = 0; acc[i][3] = 0; }

    for (int k0 = 0; k0 < K; k0 += 8) {
        float4 av = *(const float4*)(Ap + k0);
        float4 wv = *(const float4*)(Wp + k0);
        __syncthreads();
        As[lseg + 0][lrow] = av.x; As[lseg + 1][lrow] = av.y;
        As[lseg + 2][lrow] = av.z; As[lseg + 3][lrow] = av.w;
        Ws[lseg + 0][lrow] = wv.x; Ws[lseg + 1][lrow] = wv.y;
        Ws[lseg + 2][lrow] = wv.z; Ws[lseg + 3][lrow] = wv.w;
        __syncthreads();
#pragma unroll
        for (int kk = 0; kk < 8; kk++) {
            float4 a0 = *(const float4*)&As[kk][ty * 8];
            float4 a1 = *(const float4*)&As[kk][ty * 8 + 4];
            float4 b0 = *(const float4*)&Ws[kk][tx * 8];
            float4 b1 = *(const float4*)&Ws[kk][tx * 8 + 4];
            ull bp0 = pack2(b0.x, b0.y), bp1 = pack2(b0.z, b0.w);
            ull bp2 = pack2(b1.x, b1.y), bp3 = pack2(b1.z, b1.w);
            float aa[8] = {a0.x, a0.y, a0.z, a0.w, a1.x, a1.y, a1.z, a1.w};
#pragma unroll
            for (int i = 0; i < 8; i++) {
                ull a2 = splat2(aa[i]);
                acc[i][0] = ffma2(a2, bp0, acc[i][0]);
                acc[i][1] = ffma2(a2, bp1, acc[i][1]);
                acc[i][2] = ffma2(a2, bp2, acc[i][2]);
                acc[i][3] = ffma2(a2, bp3, acc[i][3]);
            }
        }
    }
    float bs[8];
#pragma unroll
    for (int j = 0; j < 8; j++) bs[j] = bias[n0 + tx * 8 + j];
#pragma unroll
    for (int i = 0; i < 8; i++) {
        float* Crow = C + (size_t)(m0 + ty * 8 + i) * G4 + n0 + tx * 8;
        float4 v0 = make_float4(lo2(acc[i][0]) + bs[0], hi2(acc[i][0]) + bs[1],
                                lo2(acc[i][1]) + bs[2], hi2(acc[i][1]) + bs[3]);
        float4 v1 = make_float4(lo2(acc[i][2]) + bs[4], hi2(acc[i][2]) + bs[5],
                                lo2(acc[i][3]) + bs[6], hi2(acc[i][3]) + bs[7]);
        *(float4*)(Crow) = v0;
        *(float4*)(Crow + 4) = v1;
    }
}

// ---------------- fused persistent scan, flag-based per-dir sync ----------------
#define SW_STRIDE 514   // float4 per hc weight row (512 + pad)
#define RED_STRIDE 33   // float4 per (kc,hc) reduction row (32 + pad)

__global__ void __launch_bounds__(256, 1) lstm_scan(int layer, float* __restrict__ out,
                                                    const float* __restrict__ mask_h) {
    extern __shared__ __align__(16) float4 smem4[];
    float4* sw4   = smem4;                       // 8 * 514  float4
    float4* s_hm4 = smem4 + 8 * SW_STRIDE;       // 4096 float4
    float4* red4  = s_hm4 + 4096;                // 128 * 33 float4

    const int bx = blockIdx.x;
    const int tid = threadIdx.x;
    const int dirb = bx >> 6;
    const int jt = bx & 63;

    // phase1 thread identity
    const int kc  = tid >> 4;                    // 0..15 : 32-k chunk
    const int hcp = (tid >> 2) & 3;              // hc pair
    const int bq  = tid & 3;                     // 8-b group
    const int sub = tid & 15;                    // lane within kc group

    // load weight slice into SMEM once
    {
        const float4* whhT4 = (const float4*)g_whhT;
        const size_t rowbase = ((size_t)(layer * 2 + dirb) * 512 + jt * 8) * 512;
        for (int idx = tid; idx < 4096; idx += 256) {
            int r = idx >> 9, k = idx & 511;
            sw4[r * SW_STRIDE + k] = whhT4[rowbase + (size_t)r * 512 + k];
        }
    }

    // phase2 thread identity
    const int hc_local = tid >> 5;
    const int b2 = tid & 31;
    const int hcg = jt * 8 + hc_local;
    const float mh = mask_h[(size_t)layer * 16384 + b2 * 512 + hcg];
    float h_reg = 0.f, c_reg = 0.f;

    // reset own flag + init read buffer h(-1)=0; single atomic barrier makes it visible
    if (tid == 0) *(volatile unsigned*)&g_flags[(dirb * 64 + jt) * 32] = 0u;
    g_hmT[1][dirb * 16384 + hcg * 32 + b2] = 0.f;
    grid_barrier();

    volatile unsigned* myflags = (volatile unsigned*)(g_flags + dirb * 64 * 32);
    const float4* wrow0 = sw4 + (hcp * 2) * SW_STRIDE + kc * 32;
    const float4* wrow1 = wrow0 + SW_STRIDE;
    const float4* hrow  = s_hm4 + kc * 256 + bq * 2;
    const int lane = tid & 31;

    for (int s = 0; s < TT; s++) {
        const int t = dirb ? (TT - 1 - s) : s;

        // prefetch xg gates (DRAM latency hidden under wait+GEMM)
        const float* xgb = g_xg + ((size_t)dirb * TBM + (size_t)t * BB + b2) * G4 + hcg;
        float xi = __ldcg(xgb);
        float xf = __ldcg(xgb + HH);
        float xg_ = __ldcg(xgb + 2 * HH);
        float xo = __ldcg(xgb + 3 * HH);

        // wait for all same-dir producers of h(s-1): every warp polls independently
        if (s > 0) {
            unsigned tgt = (unsigned)s;
            while (myflags[lane * 32] < tgt || myflags[(lane + 32) * 32] < tgt) {}
        }
        __syncwarp();

        // stage own kc region of h(s-1) (only this half-warp reads it)
        const float4* hb = (const float4*)(g_hmT[(s + 1) & 1]) + dirb * 4096 + kc * 256;
#pragma unroll
        for (int i = 0; i < 16; i++)
            s_hm4[kc * 256 + i * 16 + sub] = __ldcg(hb + i * 16 + sub);
        __syncwarp();

        // recurrent GEMM over this thread's 32-k chunk
        ull a0[8][2], a1[8][2];
#pragma unroll
        for (int i = 0; i < 8; i++) { a0[i][0] = 0; a0[i][1] = 0; a1[i][0] = 0; a1[i][1] = 0; }

#pragma unroll 4
        for (int kk = 0; kk < 32; kk++) {
            ulonglong2 w0 = *(const ulonglong2*)(wrow0 + kk);   // .x = gates i,f ; .y = g,o
            ulonglong2 w1 = *(const ulonglong2*)(wrow1 + kk);
            float4 hA = hrow[kk * 8];
            float4 hB = hrow[kk * 8 + 1];
            float hv[8] = {hA.x, hA.y, hA.z, hA.w, hB.x, hB.y, hB.z, hB.w};
#pragma unroll
            for (int ib = 0; ib < 8; ib++) {
                ull h2 = splat2(hv[ib]);
                a0[ib][0] = ffma2(h2, w0.x, a0[ib][0]);
                a0[ib][1] = ffma2(h2, w0.y, a0[ib][1]);
                a1[ib][0] = ffma2(h2, w1.x, a1[ib][0]);
                a1[ib][1] = ffma2(h2, w1.y, a1[ib][1]);
            }
        }

        // partials -> padded SMEM reduction buffer
        {
            float4* r0 = red4 + (size_t)(kc * 8 + hcp * 2) * RED_STRIDE + bq * 8;
            float4* r1 = r0 + RED_STRIDE;
#pragma unroll
            for (int ib = 0; ib < 8; ib++) {
                r0[ib] = make_float4(lo2(a0[ib][0]), hi2(a0[ib][0]), lo2(a0[ib][1]), hi2(a0[ib][1]));
                r1[ib] = make_float4(lo2(a1[ib][0]), hi2(a1[ib][0]), lo2(a1[ib][1]), hi2(a1[ib][1]));
            }
        }
        __syncthreads();

        // in-block reduce + pointwise LSTM
        float gi = xi, gf = xf, gg = xg_, go = xo;
#pragma unroll
        for (int k16 = 0; k16 < 16; k16++) {
            float4 v = red4[(size_t)(k16 * 8 + hc_local) * RED_STRIDE + b2];
            gi += v.x; gf += v.y; gg += v.z; go += v.w;
        }
        c_reg = fast_sigmoid(gf) * c_reg + fast_sigmoid(gi) * fast_tanh(gg);
        h_reg = fast_sigmoid(go) * fast_tanh(c_reg);

        // critical-path store only; release once per block (cumulative via syncthreads)
        __stcg(&g_hmT[s & 1][dirb * 16384 + hcg * 32 + b2], h_reg * mh);
        __syncthreads();
        if (tid == 0) {
            asm volatile("fence.acq_rel.gpu;" ::: "memory");
            myflags[jt * 32] = (unsigned)(s + 1);
        }

        // off-path output stores after the signal
        if (layer == 0)
            g_y[(size_t)dirb * TBM * HH + ((size_t)t * BB + b2) * HH + hcg] = h_reg;
        else
            out[((size_t)b2 * TT + t) * (2 * HH) + dirb * HH + hcg] = h_reg;
    }

    // final hn / cn from registers: [layer*2+dir][b][h]
    out[OUT_HN + (size_t)layer * 32768 + dirb * 16384 + b2 * 512 + hcg] = h_reg;
    out[OUT_CN + (size_t)layer * 32768 + dirb * 16384 + b2 * 512 + hcg] = c_reg;
}

// ---------------- launcher ----------------
extern "C" void kernel_launch(void* const* d_in, const int* in_sizes, int n_in,
                              void* d_out, int out_size) {
    (void)in_sizes; (void)n_in; (void)out_size;
    const float* x       = (const float*)d_in[0];
    const float* mask_x  = (const float*)d_in[1];
    const float* mask_out= (const float*)d_in[2];
    const float* mask_h  = (const float*)d_in[3];
    const float* w_ih_l0 = (const float*)d_in[4];
    const float* w_hh_l0 = (const float*)d_in[5];
    const float* b_l0    = (const float*)d_in[6];
    const float* w_ih_l1 = (const float*)d_in[7];
    const float* w_hh_l1 = (const float*)d_in[8];
    const float* b_l1    = (const float*)d_in[9];
    float* out = (float*)d_out;

    float *p_xm = nullptr, *p_xg = nullptr;
    cudaGetSymbolAddress((void**)&p_xm, g_xm);
    cudaGetSymbolAddress((void**)&p_xg, g_xg);

    const int scan_smem = (8 * SW_STRIDE + 4096 + 128 * RED_STRIDE) * 16;  // 198912 B
    cudaFuncSetAttribute(lstm_scan, cudaFuncAttributeMaxDynamicSharedMemorySize, scan_smem);

    // launches #1..#5 (shim: scan(0) is launch #6 -> captured by ncu -s 5 -c 1)
    k_build_whhT<<<4194304 / 256, 256>>>(w_hh_l0, w_hh_l1);
    k_mask_in0<<<16384, 256>>>(x, mask_x, 0);
    k_mask_in0<<<16384, 256>>>(x, mask_x, 4194304);

    for (int dir = 0; dir < 2; dir++)
        gemm_nt_bias<<<dim3(16, 128), 256>>>(p_xm, w_ih_l0 + (size_t)dir * G4 * DD,
                                             b_l0 + dir * G4,
                                             p_xg + (size_t)dir * TBM * G4, DD);

    lstm_scan<<<NBLK, 256, scan_smem>>>(0, out, mask_h);     // launch #6

    k_build_in1<<<16777216 / 256, 256>>>(mask_out);
    for (int dir = 0; dir < 2; dir++)
        gemm_nt_bias<<<dim3(16, 128), 256>>>(p_xm, w_ih_l1 + (size_t)dir * G4 * (2 * HH),
                                             b_l1 + dir * G4,
                                             p_xg + (size_t)dir * TBM * G4, 2 * HH);

    lstm_scan<<<NBLK, 256, scan_smem>>>(1, out, mask_h);
}